// round 11
// baseline (speedup 1.0000x reference)
#include <cuda_runtime.h>

// ---------------------------------------------------------------------------
// EquivariantAttention — fp32 persistent kernel, 1 block/SM, 512 threads.
// Prefetch-pipelined node loop; float4 LDS in layer2; fused attention tail.
// ---------------------------------------------------------------------------

namespace {

constexpr int NODES = 20000;
constexpr int NBR   = 16;
constexpr int MULT  = 8;
constexpr int DIMV  = 4;
constexpr int EDIM  = 32;
constexpr int HIDN  = 64;
constexpr int FLAT  = 256;   // (NL*MULT)^2
constexpr float ATT_SCALE = 0.35355339059327373f;   // 8^-0.5

struct alignas(16) SmemT {
    // weights (loaded once per block)
    float w2s[2][HIDN * FLAT];   // repacked: row c -> [ihalf*128 + low4*8 + jj]
    float w1s[2][EDIM * HIDN];   // [br][i*64 + c]
    float b1s[2][HIDN];
    float b2s[2][FLAT];
    float qw[16 * 8];
    float ow[16 * 8];
    float qb[8];
    float ob[8];
    // per-node input set (double-buffered for the prefetch pipeline)
    float ef[2][16][32];
    float fsrc[2][16][32];
    float fnode[2][32];
    float bas1[2][2][16][8];     // [buf][br][e][d*2+l]
    float bas2[2][2][16][8];     // [buf][br][e][l*4+d]
    // per-node intermediates
    float hbuf[2][16][HIDN];
    float tmpb[2][16][16];       // [br][e][m*2+l]
    float t2b[2][16][16];        // [br][e][m*2+l]
    float qvec[32];
    float ao[32];
};

__device__ __forceinline__ void p3step(float rw[4][8],
                                       float h0, float h1, float h2, float h3,
                                       float4 wa, float4 wb) {
    float w[8] = {wa.x, wa.y, wa.z, wa.w, wb.x, wb.y, wb.z, wb.w};
    float hv[4] = {h0, h1, h2, h3};
    #pragma unroll
    for (int k = 0; k < 4; k++)
        #pragma unroll
        for (int j = 0; j < 8; j++)
            rw[k][j] = fmaf(hv[k], w[j], rw[k][j]);
}

} // namespace

__global__ __launch_bounds__(512, 1)
void eqattn_kernel(
    const float* __restrict__ bk1, const float* __restrict__ bk2,
    const float* __restrict__ bv1, const float* __restrict__ bv2,
    const float* __restrict__ efeat, const float* __restrict__ fin,
    const float* __restrict__ q_w,  const float* __restrict__ q_b,
    const float* __restrict__ k_w1, const float* __restrict__ k_b1,
    const float* __restrict__ k_w2, const float* __restrict__ k_b2,
    const float* __restrict__ v_w1, const float* __restrict__ v_b1,
    const float* __restrict__ v_w2, const float* __restrict__ v_b2,
    const float* __restrict__ o_w,  const float* __restrict__ o_b,
    const int*   __restrict__ nidx32,
    float* __restrict__ out)
{
    extern __shared__ unsigned char smem_raw[];
    SmemT& S = *reinterpret_cast<SmemT*>(smem_raw);
    const int tid = threadIdx.x;

    // int64 vs int32 neighbor_idx sniff (little-endian high words are 0)
    const bool is64 = (nidx32[1] == 0 && nidx32[3] == 0 &&
                       nidx32[5] == 0 && nidx32[7] == 0);
    const long long* nidx64 = reinterpret_cast<const long long*>(nidx32);

    // ---------------- prologue: stage all weights into smem ----------------
    // w2 repack: value (c, p), p = i*16 + j. ihalf=i>>3, r3=i&7, jh=j>>3, jj=j&7,
    // low4=r3*2+jh. Stored at pos = ihalf*128 + low4*8 + jj so each lane's 8
    // j-values are contiguous (two float4 loads per c).
    for (int t = tid; t < 2 * HIDN * FLAT; t += 512) {
        int br  = t >> 14;
        int rem = t & 16383;           // c*256 + p
        int p   = rem & 255;
        const float* g = br ? v_w2 : k_w2;
        float val = g[rem];
        int i  = p >> 4;
        int j  = p & 15;
        int pos = ((i >> 3) << 7) + (((((i & 7) << 1) | (j >> 3))) << 3) + (j & 7);
        S.w2s[br][(rem & ~255) + pos] = val;
    }
    for (int t = tid; t < 2 * EDIM * HIDN; t += 512) {
        int br = t >> 11;
        int rem = t & 2047;
        S.w1s[br][rem] = (br ? v_w1 : k_w1)[rem];
    }
    {
        int br = tid >> 8, p = tid & 255;
        S.b2s[br][p] = (br ? v_b2 : k_b2)[p];
    }
    if (tid < 128) {
        int br = tid >> 6;
        S.b1s[br][tid & 63] = (br ? v_b1 : k_b1)[tid & 63];
        S.qw[tid] = q_w[tid];
        S.ow[tid] = o_w[tid];
    }
    if (tid < 8) { S.qb[tid] = q_b[tid]; S.ob[tid] = o_b[tid]; }

    // prefetch thread roles (fixed over the loop)
    const int pe   = tid >> 5, pi = tid & 31;       // ef / fsrc element
    const int parr = tid >> 7;                      // which basis array
    const int peb  = (tid >> 3) & 15, px = tid & 7; // basis element

    // ------------- prologue: load node n0's inputs into buffer 0 -----------
    {
        const int n0 = blockIdx.x;
        int ib = n0 * NBR + pe;
        int iv = is64 ? (int)nidx64[ib] : nidx32[ib];
        S.ef[0][pe][pi]   = efeat[n0 * (NBR * EDIM) + tid];
        S.fsrc[0][pe][pi] = fin[iv * (MULT * DIMV) + pi];
        const float* psrc = (parr == 0) ? bk1 : (parr == 1) ? bk2
                          : (parr == 2) ? bv1 : bv2;
        float bv = psrc[n0 * (NBR * 8) + peb * 8 + px];
        if (parr == 0)      S.bas1[0][0][peb][px] = bv;
        else if (parr == 1) S.bas2[0][0][peb][px] = bv;
        else if (parr == 2) S.bas1[0][1][peb][px] = bv;
        else                S.bas2[0][1][peb][px] = bv;
        if (tid < 32) S.fnode[0][tid] = fin[n0 * (MULT * DIMV) + tid];
    }
    __syncthreads();

    // layer2 thread geometry (constant over node loop)
    const int warp  = tid >> 5;
    const int lane  = tid & 31;
    const int brw   = warp >> 3;         // branch for layer2 (0=k,1=v)
    const int wb    = warp & 7;
    const int eg2   = wb >> 1;           // edges eg2 + {0,4,8,12}
    const int ihalf = wb & 1;
    const int chalf = lane >> 4;         // 0/1: which half of c in [0,64)
    const int low4  = lane & 15;         // == (irow&7)*2 + jh  (matches repack)
    const int jh    = low4 & 1;
    const int irow  = (ihalf << 3) + (low4 >> 1);   // i in 0..15

    // ---------------------------- node loop --------------------------------
    int pb = 0;
    for (int n = blockIdx.x; n < NODES; n += gridDim.x, pb ^= 1) {

        // ---- issue next node's global loads (consumed at end of iteration)
        const int n2 = n + (int)gridDim.x;
        const bool pf = (n2 < NODES);
        float pf_ef = 0.0f, pf_fs = 0.0f, pf_bas = 0.0f, pf_fn = 0.0f;
        if (pf) {
            int ib = n2 * NBR + pe;
            int iv = is64 ? (int)nidx64[ib] : nidx32[ib];
            pf_ef = efeat[n2 * (NBR * EDIM) + tid];
            pf_fs = fin[iv * (MULT * DIMV) + pi];
            const float* psrc = (parr == 0) ? bk1 : (parr == 1) ? bk2
                              : (parr == 2) ? bv1 : bv2;
            pf_bas = psrc[n2 * (NBR * 8) + peb * 8 + px];
            if (tid < 32) pf_fn = fin[n2 * (MULT * DIMV) + tid];
        }

        // phase 2: layer1 (h = gelu(ef@w1+b1)), tmp (f_src x bas1), q
        {
            const int br  = tid >> 8;
            const int rem = tid & 255;
            const int c   = rem & 63;
            const int eg  = rem >> 6;        // 0..3, edges eg+4k
            float acc0, acc1, acc2, acc3;
            acc0 = acc1 = acc2 = acc3 = S.b1s[br][c];
            #pragma unroll
            for (int i4 = 0; i4 < EDIM; i4 += 4) {
                float wa = S.w1s[br][(i4 + 0) * HIDN + c];
                float wbv = S.w1s[br][(i4 + 1) * HIDN + c];
                float wc = S.w1s[br][(i4 + 2) * HIDN + c];
                float wd = S.w1s[br][(i4 + 3) * HIDN + c];
                float4 e0 = *reinterpret_cast<const float4*>(&S.ef[pb][eg +  0][i4]);
                float4 e1 = *reinterpret_cast<const float4*>(&S.ef[pb][eg +  4][i4]);
                float4 e2 = *reinterpret_cast<const float4*>(&S.ef[pb][eg +  8][i4]);
                float4 e3 = *reinterpret_cast<const float4*>(&S.ef[pb][eg + 12][i4]);
                acc0 = fmaf(e0.x, wa, acc0); acc0 = fmaf(e0.y, wbv, acc0);
                acc0 = fmaf(e0.z, wc, acc0); acc0 = fmaf(e0.w, wd, acc0);
                acc1 = fmaf(e1.x, wa, acc1); acc1 = fmaf(e1.y, wbv, acc1);
                acc1 = fmaf(e1.z, wc, acc1); acc1 = fmaf(e1.w, wd, acc1);
                acc2 = fmaf(e2.x, wa, acc2); acc2 = fmaf(e2.y, wbv, acc2);
                acc2 = fmaf(e2.z, wc, acc2); acc2 = fmaf(e2.w, wd, acc2);
                acc3 = fmaf(e3.x, wa, acc3); acc3 = fmaf(e3.y, wbv, acc3);
                acc3 = fmaf(e3.z, wc, acc3); acc3 = fmaf(e3.w, wd, acc3);
            }
            // exact gelu: x * Phi(x)
            S.hbuf[br][eg +  0][c] = acc0 * normcdff(acc0);
            S.hbuf[br][eg +  4][c] = acc1 * normcdff(acc1);
            S.hbuf[br][eg +  8][c] = acc2 * normcdff(acc2);
            S.hbuf[br][eg + 12][c] = acc3 * normcdff(acc3);
        }
        {
            const int br = tid >> 8;
            const int rem = tid & 255;
            const int e = rem >> 4;
            const int j = rem & 15;          // m*2 + l
            const int m = j >> 1, l = j & 1;
            const float* fr = S.fsrc[pb][e];
            const float* b  = S.bas1[pb][br][e];
            float t = fr[m * 4 + 0] * b[0 * 2 + l];
            t = fmaf(fr[m * 4 + 1], b[1 * 2 + l], t);
            t = fmaf(fr[m * 4 + 2], b[2 * 2 + l], t);
            t = fmaf(fr[m * 4 + 3], b[3 * 2 + l], t);
            S.tmpb[br][e][j] = t;
        }
        if (tid < 32) {
            const int m = tid >> 2, d = tid & 3;
            const int l = (d == 0) ? 0 : 1;
            float a = (d == 0) ? S.qb[m] : 0.0f;
            #pragma unroll
            for (int mp = 0; mp < MULT; mp++)
                a = fmaf(S.qw[(l * MULT + m) * MULT + mp], S.fnode[pb][mp * 4 + d], a);
            S.qvec[tid] = a;
        }
        __syncthreads();

        // phase 3: layer2 — rw = h@w2 + b2 (c split across half-warps), float4
        // loads for both w2 (lane-contiguous) and h (broadcast); then t2 = rw@tmp.
        {
            float rw[4][8];
            {
                const int p0 = (irow << 4) + (jh << 3);
                #pragma unroll
                for (int j = 0; j < 8; j++) {
                    float bb = (chalf == 0) ? S.b2s[brw][p0 + j] : 0.0f;
                    rw[0][j] = bb; rw[1][j] = bb; rw[2][j] = bb; rw[3][j] = bb;
                }
            }
            const float4* w2q = reinterpret_cast<const float4*>(
                &S.w2s[brw][(ihalf << 7) + (low4 << 3)]);   // stride 64 float4 per c
            const float* h0p = S.hbuf[brw][eg2 +  0];
            const float* h1p = S.hbuf[brw][eg2 +  4];
            const float* h2p = S.hbuf[brw][eg2 +  8];
            const float* h3p = S.hbuf[brw][eg2 + 12];
            const int c0 = chalf << 5;
            #pragma unroll 2
            for (int cb = 0; cb < 32; cb += 4) {
                const int c = c0 + cb;
                float4 a0 = *reinterpret_cast<const float4*>(&h0p[c]);
                float4 a1 = *reinterpret_cast<const float4*>(&h1p[c]);
                float4 a2 = *reinterpret_cast<const float4*>(&h2p[c]);
                float4 a3 = *reinterpret_cast<const float4*>(&h3p[c]);
                p3step(rw, a0.x, a1.x, a2.x, a3.x, w2q[(c+0)*64], w2q[(c+0)*64+1]);
                p3step(rw, a0.y, a1.y, a2.y, a3.y, w2q[(c+1)*64], w2q[(c+1)*64+1]);
                p3step(rw, a0.z, a1.z, a2.z, a3.z, w2q[(c+2)*64], w2q[(c+2)*64+1]);
                p3step(rw, a0.w, a1.w, a2.w, a3.w, w2q[(c+3)*64], w2q[(c+3)*64+1]);
            }
            #pragma unroll
            for (int k = 0; k < 4; k++) {
                const int e = eg2 + 4 * k;
                const float* tp = &S.tmpb[brw][e][jh << 3];
                float acc = 0.0f;
                #pragma unroll
                for (int j = 0; j < 8; j++) acc = fmaf(rw[k][j], tp[j], acc);
                acc += __shfl_xor_sync(0xffffffffu, acc, 16);  // fold c-halves
                acc += __shfl_xor_sync(0xffffffffu, acc, 1);   // fold j-halves
                if ((lane & 17) == 0) S.t2b[brw][e][irow] = acc;
            }
        }
        __syncthreads();

        // fused phases 4-6: per (head, k) thread builds k/v from t2 x bas2,
        // computes logits, softmax, and attn-weighted V; folds to ao.
        if (tid < 64) {
            const int h = tid >> 4, kk = tid & 15;
            // t2 quads for this head: indices 4h..4h+3 = (m=2h,l=0/1),(m=2h+1,l=0/1)
            float4 tk = *reinterpret_cast<const float4*>(&S.t2b[0][kk][4 * h]);
            float4 tv = *reinterpret_cast<const float4*>(&S.t2b[1][kk][4 * h]);
            float4 bkl0 = *reinterpret_cast<const float4*>(&S.bas2[pb][0][kk][0]);
            float4 bkl1 = *reinterpret_cast<const float4*>(&S.bas2[pb][0][kk][4]);
            float4 bvl0 = *reinterpret_cast<const float4*>(&S.bas2[pb][1][kk][0]);
            float4 bvl1 = *reinterpret_cast<const float4*>(&S.bas2[pb][1][kk][4]);
            // k components (dd = 0..7 -> m = 2h + (dd>>2), d = dd&3)
            float kv0 = fmaf(tk.y, bkl1.x, tk.x * bkl0.x);
            float kv1 = fmaf(tk.y, bkl1.y, tk.x * bkl0.y);
            float kv2 = fmaf(tk.y, bkl1.z, tk.x * bkl0.z);
            float kv3 = fmaf(tk.y, bkl1.w, tk.x * bkl0.w);
            float kv4 = fmaf(tk.w, bkl1.x, tk.z * bkl0.x);
            float kv5 = fmaf(tk.w, bkl1.y, tk.z * bkl0.y);
            float kv6 = fmaf(tk.w, bkl1.z, tk.z * bkl0.z);
            float kv7 = fmaf(tk.w, bkl1.w, tk.z * bkl0.w);
            float4 q0 = *reinterpret_cast<const float4*>(&S.qvec[h * 8]);
            float4 q1 = *reinterpret_cast<const float4*>(&S.qvec[h * 8 + 4]);
            float acc = q0.x * kv0;
            acc = fmaf(q0.y, kv1, acc); acc = fmaf(q0.z, kv2, acc);
            acc = fmaf(q0.w, kv3, acc); acc = fmaf(q1.x, kv4, acc);
            acc = fmaf(q1.y, kv5, acc); acc = fmaf(q1.z, kv6, acc);
            acc = fmaf(q1.w, kv7, acc);
            acc *= ATT_SCALE;
            float mx = acc;
            #pragma unroll
            for (int o = 8; o >= 1; o >>= 1)
                mx = fmaxf(mx, __shfl_xor_sync(0xffffffffu, mx, o));
            float ex = expf(acc - mx);
            float sm = ex;
            #pragma unroll
            for (int o = 8; o >= 1; o >>= 1)
                sm += __shfl_xor_sync(0xffffffffu, sm, o);
            const float at = ex / sm;
            // v components, weighted by attn
            float pv[8];
            pv[0] = at * fmaf(tv.y, bvl1.x, tv.x * bvl0.x);
            pv[1] = at * fmaf(tv.y, bvl1.y, tv.x * bvl0.y);
            pv[2] = at * fmaf(tv.y, bvl1.z, tv.x * bvl0.z);
            pv[3] = at * fmaf(tv.y, bvl1.w, tv.x * bvl0.w);
            pv[4] = at * fmaf(tv.w, bvl1.x, tv.z * bvl0.x);
            pv[5] = at * fmaf(tv.w, bvl1.y, tv.z * bvl0.y);
            pv[6] = at * fmaf(tv.w, bvl1.z, tv.z * bvl0.z);
            pv[7] = at * fmaf(tv.w, bvl1.w, tv.z * bvl0.w);
            #pragma unroll
            for (int o = 8; o >= 1; o >>= 1) {
                #pragma unroll
                for (int j = 0; j < 8; j++)
                    pv[j] += __shfl_xor_sync(0xffffffffu, pv[j], o);
            }
            #pragma unroll
            for (int dd = 0; dd < 8; dd++)
                if (kk == dd) S.ao[h * 8 + dd] = pv[dd];
        }
        __syncthreads();

        // phase 7: final eq_linear -> global
        if (tid < 32) {
            const int m = tid >> 2, d = tid & 3;
            const int l = (d == 0) ? 0 : 1;
            float a = (d == 0) ? S.ob[m] : 0.0f;
            #pragma unroll
            for (int mp = 0; mp < MULT; mp++)
                a = fmaf(S.ow[(l * MULT + m) * MULT + mp], S.ao[mp * 4 + d], a);
            out[n * 32 + tid] = a;
        }

        // ---- commit next node's inputs into the other buffer, then publish
        if (pf) {
            const int nb = pb ^ 1;
            S.ef[nb][pe][pi]   = pf_ef;
            S.fsrc[nb][pe][pi] = pf_fs;
            if (parr == 0)      S.bas1[nb][0][peb][px] = pf_bas;
            else if (parr == 1) S.bas2[nb][0][peb][px] = pf_bas;
            else if (parr == 2) S.bas1[nb][1][peb][px] = pf_bas;
            else                S.bas2[nb][1][peb][px] = pf_bas;
            if (tid < 32) S.fnode[nb][tid] = pf_fn;
        }
        __syncthreads();
    }
}

extern "C" void kernel_launch(void* const* d_in, const int* in_sizes, int n_in,
                              void* d_out, int out_size) {
    const float* bk1  = (const float*)d_in[0];
    const float* bk2  = (const float*)d_in[1];
    const float* bv1  = (const float*)d_in[2];
    const float* bv2  = (const float*)d_in[3];
    const float* ef   = (const float*)d_in[4];
    const float* fin  = (const float*)d_in[5];
    const float* q_w  = (const float*)d_in[6];
    const float* q_b  = (const float*)d_in[7];
    const float* k_w1 = (const float*)d_in[8];
    const float* k_b1 = (const float*)d_in[9];
    const float* k_w2 = (const float*)d_in[10];
    const float* k_b2 = (const float*)d_in[11];
    const float* v_w1 = (const float*)d_in[12];
    const float* v_b1 = (const float*)d_in[13];
    const float* v_w2 = (const float*)d_in[14];
    const float* v_b2 = (const float*)d_in[15];
    const float* o_w  = (const float*)d_in[16];
    const float* o_b  = (const float*)d_in[17];
    const int*   nidx = (const int*)d_in[18];
    float* out = (float*)d_out;

    int sms = 148;
    cudaDeviceGetAttribute(&sms, cudaDevAttrMultiProcessorCount, 0);
    if (sms <= 0) sms = 148;

    const int smem = (int)sizeof(SmemT);
    cudaFuncSetAttribute(eqattn_kernel,
                         cudaFuncAttributeMaxDynamicSharedMemorySize, smem);

    eqattn_kernel<<<sms, 512, smem>>>(
        bk1, bk2, bv1, bv2, ef, fin,
        q_w, q_b, k_w1, k_b1, k_w2, k_b2,
        v_w1, v_b1, v_w2, v_b2, o_w, o_b,
        nidx, out);
}

// round 12
// speedup vs baseline: 1.2951x; 1.2951x over previous
#include <cuda_runtime.h>

// ---------------------------------------------------------------------------
// EquivariantAttention — fp32 persistent kernel, 1 block/SM, 512 threads.
// R8 structure (prefetch-pipelined node loop, float2 w2 LDS) with phase-3
// arithmetic packed as fma.rn.f32x2 built from registers (loads unchanged).
// ---------------------------------------------------------------------------

namespace {

constexpr int NODES = 20000;
constexpr int NBR   = 16;
constexpr int MULT  = 8;
constexpr int DIMV  = 4;
constexpr int EDIM  = 32;
constexpr int HIDN  = 64;
constexpr int FLAT  = 256;   // (NL*MULT)^2
constexpr float ATT_SCALE = 0.35355339059327373f;   // 8^-0.5

struct alignas(16) SmemT {
    // weights (loaded once per block)
    float w2s[2][HIDN * FLAT];   // repacked swizzled layout (see pos calc)
    float w1s[2][EDIM * HIDN];   // [br][i*64 + c]
    float b1s[2][HIDN];
    float b2s[2][FLAT];
    float qw[16 * 8];
    float ow[16 * 8];
    float qb[8];
    float ob[8];
    // per-node input set (double-buffered for the prefetch pipeline)
    float ef[2][16][32];
    float fsrc[2][16][32];
    float fnode[2][32];
    float bas1[2][2][16][8];     // [buf][br][e][d*2+l]
    float bas2[2][2][16][8];     // [buf][br][e][l*4+d]
    // per-node intermediates (single-buffered)
    float hbuf[2][16][HIDN];
    float tmpb[2][16][16];       // [br][e][m*2+l]
    float t2b[2][16][16];        // [br][e][o*2+l]
    float kvb[2][16][32];        // [br][e][m*4+d]
    float qvec[32];
    float attn[4][16];
    float ao[32];
};

__device__ __forceinline__ unsigned long long ffma2(
    unsigned long long a, unsigned long long b, unsigned long long c) {
    unsigned long long d;
    asm("fma.rn.f32x2 %0, %1, %2, %3;" : "=l"(d) : "l"(a), "l"(b), "l"(c));
    return d;
}
__device__ __forceinline__ unsigned long long fmul2(
    unsigned long long a, unsigned long long b) {
    unsigned long long d;
    asm("mul.rn.f32x2 %0, %1, %2;" : "=l"(d) : "l"(a), "l"(b));
    return d;
}
__device__ __forceinline__ unsigned long long pack2(float x) {
    unsigned long long d;
    asm("mov.b64 %0, {%1, %1};" : "=l"(d) : "f"(x));
    return d;
}

} // namespace

__global__ __launch_bounds__(512, 1)
void eqattn_kernel(
    const float* __restrict__ bk1, const float* __restrict__ bk2,
    const float* __restrict__ bv1, const float* __restrict__ bv2,
    const float* __restrict__ efeat, const float* __restrict__ fin,
    const float* __restrict__ q_w,  const float* __restrict__ q_b,
    const float* __restrict__ k_w1, const float* __restrict__ k_b1,
    const float* __restrict__ k_w2, const float* __restrict__ k_b2,
    const float* __restrict__ v_w1, const float* __restrict__ v_b1,
    const float* __restrict__ v_w2, const float* __restrict__ v_b2,
    const float* __restrict__ o_w,  const float* __restrict__ o_b,
    const int*   __restrict__ nidx32,
    float* __restrict__ out)
{
    extern __shared__ unsigned char smem_raw[];
    SmemT& S = *reinterpret_cast<SmemT*>(smem_raw);
    const int tid = threadIdx.x;

    // int64 vs int32 neighbor_idx sniff (little-endian high words are 0)
    const bool is64 = (nidx32[1] == 0 && nidx32[3] == 0 &&
                       nidx32[5] == 0 && nidx32[7] == 0);
    const long long* nidx64 = reinterpret_cast<const long long*>(nidx32);

    // ---------------- prologue: stage all weights into smem ----------------
    // w2 repack: value (c, p) with p = i*16 + jh*8 + jq*2 + r.
    // lane_r = (i&7)*2 + jh (0..15). Stored at
    //   pos = (i>>3)*128 + jq*32 + lane_r*2 + r
    // so a 16-lane group's float2 reads per (c, jq) are 128B contiguous.
    for (int t = tid; t < 2 * HIDN * FLAT; t += 512) {
        int br  = t >> 14;
        int rem = t & 16383;           // c*256 + p
        int p   = rem & 255;
        const float* g = br ? v_w2 : k_w2;
        float val = g[rem];
        int i  = p >> 4;
        int jh = (p >> 3) & 1;
        int jq = (p >> 1) & 3;
        int r  = p & 1;
        int pos = ((i >> 3) << 7) + (jq << 5) + ((((i & 7) << 1) | jh) << 1) + r;
        S.w2s[br][(rem & ~255) + pos] = val;
    }
    for (int t = tid; t < 2 * EDIM * HIDN; t += 512) {
        int br = t >> 11;
        int rem = t & 2047;
        S.w1s[br][rem] = (br ? v_w1 : k_w1)[rem];
    }
    {
        int br = tid >> 8, p = tid & 255;
        S.b2s[br][p] = (br ? v_b2 : k_b2)[p];
    }
    if (tid < 128) {
        int br = tid >> 6;
        S.b1s[br][tid & 63] = (br ? v_b1 : k_b1)[tid & 63];
        S.qw[tid] = q_w[tid];
        S.ow[tid] = o_w[tid];
    }
    if (tid < 8) { S.qb[tid] = q_b[tid]; S.ob[tid] = o_b[tid]; }

    // prefetch thread roles (fixed over the loop)
    const int pe   = tid >> 5, pi = tid & 31;       // ef / fsrc element
    const int parr = tid >> 7;                      // which basis array
    const int peb  = (tid >> 3) & 15, px = tid & 7; // basis element

    // ------------- prologue: load node n0's inputs into buffer 0 -----------
    {
        const int n0 = blockIdx.x;
        int ib = n0 * NBR + pe;
        int iv = is64 ? (int)nidx64[ib] : nidx32[ib];
        S.ef[0][pe][pi]   = efeat[n0 * (NBR * EDIM) + tid];
        S.fsrc[0][pe][pi] = fin[iv * (MULT * DIMV) + pi];
        const float* psrc = (parr == 0) ? bk1 : (parr == 1) ? bk2
                          : (parr == 2) ? bv1 : bv2;
        float bv = psrc[n0 * (NBR * 8) + peb * 8 + px];
        if (parr == 0)      S.bas1[0][0][peb][px] = bv;
        else if (parr == 1) S.bas2[0][0][peb][px] = bv;
        else if (parr == 2) S.bas1[0][1][peb][px] = bv;
        else                S.bas2[0][1][peb][px] = bv;
        if (tid < 32) S.fnode[0][tid] = fin[n0 * (MULT * DIMV) + tid];
    }
    __syncthreads();

    // layer2 thread geometry (constant over node loop)
    const int warp  = tid >> 5;
    const int lane  = tid & 31;
    const int brw   = warp >> 3;         // branch for layer2 (0=k,1=v)
    const int wb    = warp & 7;
    const int eg2   = wb >> 1;           // edges eg2 + {0,4,8,12}
    const int ihalf = wb & 1;
    const int chalf = lane >> 4;         // 0/1: which half of c in [0,64)
    const int low4  = lane & 15;         // == (irow&7)*2 + jh  (matches repack)
    const int jh    = low4 & 1;
    const int irow  = (ihalf << 3) + (low4 >> 1);   // i in 0..15

    // ---------------------------- node loop --------------------------------
    int pb = 0;
    for (int n = blockIdx.x; n < NODES; n += gridDim.x, pb ^= 1) {

        // ---- issue next node's global loads (consumed at end of iteration)
        const int n2 = n + (int)gridDim.x;
        const bool pf = (n2 < NODES);
        float pf_ef = 0.0f, pf_fs = 0.0f, pf_bas = 0.0f, pf_fn = 0.0f;
        if (pf) {
            int ib = n2 * NBR + pe;
            int iv = is64 ? (int)nidx64[ib] : nidx32[ib];
            pf_ef = efeat[n2 * (NBR * EDIM) + tid];
            pf_fs = fin[iv * (MULT * DIMV) + pi];
            const float* psrc = (parr == 0) ? bk1 : (parr == 1) ? bk2
                              : (parr == 2) ? bv1 : bv2;
            pf_bas = psrc[n2 * (NBR * 8) + peb * 8 + px];
            if (tid < 32) pf_fn = fin[n2 * (MULT * DIMV) + tid];
        }

        // phase 2: layer1 (h = gelu(ef@w1+b1)), tmp (f_src x bas1), q
        {
            const int br  = tid >> 8;
            const int rem = tid & 255;
            const int c   = rem & 63;
            const int eg  = rem >> 6;        // 0..3, edges eg+4k
            float acc0, acc1, acc2, acc3;
            acc0 = acc1 = acc2 = acc3 = S.b1s[br][c];
            #pragma unroll
            for (int i4 = 0; i4 < EDIM; i4 += 4) {
                float wa = S.w1s[br][(i4 + 0) * HIDN + c];
                float wbv = S.w1s[br][(i4 + 1) * HIDN + c];
                float wc = S.w1s[br][(i4 + 2) * HIDN + c];
                float wd = S.w1s[br][(i4 + 3) * HIDN + c];
                float4 e0 = *reinterpret_cast<const float4*>(&S.ef[pb][eg +  0][i4]);
                float4 e1 = *reinterpret_cast<const float4*>(&S.ef[pb][eg +  4][i4]);
                float4 e2 = *reinterpret_cast<const float4*>(&S.ef[pb][eg +  8][i4]);
                float4 e3 = *reinterpret_cast<const float4*>(&S.ef[pb][eg + 12][i4]);
                acc0 = fmaf(e0.x, wa, acc0); acc0 = fmaf(e0.y, wbv, acc0);
                acc0 = fmaf(e0.z, wc, acc0); acc0 = fmaf(e0.w, wd, acc0);
                acc1 = fmaf(e1.x, wa, acc1); acc1 = fmaf(e1.y, wbv, acc1);
                acc1 = fmaf(e1.z, wc, acc1); acc1 = fmaf(e1.w, wd, acc1);
                acc2 = fmaf(e2.x, wa, acc2); acc2 = fmaf(e2.y, wbv, acc2);
                acc2 = fmaf(e2.z, wc, acc2); acc2 = fmaf(e2.w, wd, acc2);
                acc3 = fmaf(e3.x, wa, acc3); acc3 = fmaf(e3.y, wbv, acc3);
                acc3 = fmaf(e3.z, wc, acc3); acc3 = fmaf(e3.w, wd, acc3);
            }
            // exact gelu: x * Phi(x)
            S.hbuf[br][eg +  0][c] = acc0 * normcdff(acc0);
            S.hbuf[br][eg +  4][c] = acc1 * normcdff(acc1);
            S.hbuf[br][eg +  8][c] = acc2 * normcdff(acc2);
            S.hbuf[br][eg + 12][c] = acc3 * normcdff(acc3);
        }
        {
            const int br = tid >> 8;
            const int rem = tid & 255;
            const int e = rem >> 4;
            const int j = rem & 15;          // m*2 + l
            const int m = j >> 1, l = j & 1;
            const float* fr = S.fsrc[pb][e];
            const float* b  = S.bas1[pb][br][e];
            float t = fr[m * 4 + 0] * b[0 * 2 + l];
            t = fmaf(fr[m * 4 + 1], b[1 * 2 + l], t);
            t = fmaf(fr[m * 4 + 2], b[2 * 2 + l], t);
            t = fmaf(fr[m * 4 + 3], b[3 * 2 + l], t);
            S.tmpb[br][e][j] = t;
        }
        if (tid < 32) {
            const int m = tid >> 2, d = tid & 3;
            const int l = (d == 0) ? 0 : 1;
            float a = (d == 0) ? S.qb[m] : 0.0f;
            #pragma unroll
            for (int mp = 0; mp < MULT; mp++)
                a = fmaf(S.qw[(l * MULT + m) * MULT + mp], S.fnode[pb][mp * 4 + d], a);
            S.qvec[tid] = a;
        }
        __syncthreads();

        // phase 3: layer2 — rw = h@w2 + b2, packed f32x2 math with R8's exact
        // load pattern (LDS.32 h broadcast + conflict-free LDS.64 w2); h dup
        // built in registers (mov.b64 {h,h}); then t2 = rw@tmp packed.
        {
            // acc2[k][jq] = packed (j=2jq, 2jq+1) pair for edge eg2+4k
            unsigned long long acc2[4][4];
            {
                const int p0 = (irow << 4) + (jh << 3);
                #pragma unroll
                for (int jq = 0; jq < 4; jq++) {
                    // bias seeded only in the chalf==0 partial sum
                    unsigned long long bb = (chalf == 0)
                        ? *reinterpret_cast<const unsigned long long*>(
                              &S.b2s[brw][p0 + 2 * jq])
                        : 0ull;
                    acc2[0][jq] = bb; acc2[1][jq] = bb;
                    acc2[2][jq] = bb; acc2[3][jq] = bb;
                }
            }
            const unsigned long long* w2p =
                reinterpret_cast<const unsigned long long*>(
                    &S.w2s[brw][(ihalf << 7) + (low4 << 1)]);
            const float* h0p = S.hbuf[brw][eg2 +  0];
            const float* h1p = S.hbuf[brw][eg2 +  4];
            const float* h2p = S.hbuf[brw][eg2 +  8];
            const float* h3p = S.hbuf[brw][eg2 + 12];
            const int c0 = chalf << 5;
            #pragma unroll 4
            for (int cc = 0; cc < 32; cc++) {
                const int c = c0 + cc;
                unsigned long long hd0 = pack2(h0p[c]);
                unsigned long long hd1 = pack2(h1p[c]);
                unsigned long long hd2 = pack2(h2p[c]);
                unsigned long long hd3 = pack2(h3p[c]);
                const unsigned long long* wc = w2p + c * 128;  // +c*256 floats
                #pragma unroll
                for (int jq = 0; jq < 4; jq++) {
                    unsigned long long w = wc[jq * 16];        // +jq*32 floats
                    acc2[0][jq] = ffma2(hd0, w, acc2[0][jq]);
                    acc2[1][jq] = ffma2(hd1, w, acc2[1][jq]);
                    acc2[2][jq] = ffma2(hd2, w, acc2[2][jq]);
                    acc2[3][jq] = ffma2(hd3, w, acc2[3][jq]);
                }
            }
            #pragma unroll
            for (int k = 0; k < 4; k++) {
                const int e = eg2 + 4 * k;
                const unsigned long long* tp =
                    reinterpret_cast<const unsigned long long*>(
                        &S.tmpb[brw][e][jh << 3]);
                unsigned long long s2 = fmul2(acc2[k][0], tp[0]);
                s2 = ffma2(acc2[k][1], tp[1], s2);
                s2 = ffma2(acc2[k][2], tp[2], s2);
                s2 = ffma2(acc2[k][3], tp[3], s2);
                float2 p2 = *reinterpret_cast<float2*>(&s2);
                float acc = p2.x + p2.y;
                acc += __shfl_xor_sync(0xffffffffu, acc, 16);  // fold c-halves
                acc += __shfl_xor_sync(0xffffffffu, acc, 1);   // fold j-halves
                if ((lane & 17) == 0) S.t2b[brw][e][irow] = acc;
            }
        }
        __syncthreads();

        // phase 4: k/v = t2 x bas2   (1024 items, 2/thread)
        #pragma unroll
        for (int rep = 0; rep < 2; rep++) {
            int it = tid + rep * 512;
            int br = it >> 9;
            int rem = it & 511;
            int e = rem >> 5;
            int p = rem & 31;                // o*4 + d
            int o = p >> 2, d = p & 3;
            float v = S.t2b[br][e][o * 2 + 0] * S.bas2[pb][br][e][0 * 4 + d];
            v = fmaf(S.t2b[br][e][o * 2 + 1], S.bas2[pb][br][e][1 * 4 + d], v);
            S.kvb[br][e][p] = v;
        }
        __syncthreads();

        // phase 5: logits + softmax (64 threads = warps 0,1; 16-lane groups)
        if (tid < 64) {
            const int h = tid >> 4, kk = tid & 15;
            float acc = 0.0f;
            #pragma unroll
            for (int dd = 0; dd < 8; dd++)
                acc = fmaf(S.qvec[h * 8 + dd], S.kvb[0][kk][h * 8 + dd], acc);
            acc *= ATT_SCALE;
            float mx = acc;
            #pragma unroll
            for (int o = 8; o >= 1; o >>= 1)
                mx = fmaxf(mx, __shfl_xor_sync(0xffffffffu, mx, o));
            float ex = expf(acc - mx);
            float sm = ex;
            #pragma unroll
            for (int o = 8; o >= 1; o >>= 1)
                sm += __shfl_xor_sync(0xffffffffu, sm, o);
            S.attn[h][kk] = ex / sm;
        }
        __syncthreads();

        // phase 6: attention output (32 threads)
        if (tid < 32) {
            const int h = tid >> 3;
            float acc = 0.0f;
            #pragma unroll
            for (int kk = 0; kk < NBR; kk++)
                acc = fmaf(S.attn[h][kk], S.kvb[1][kk][tid], acc);
            S.ao[tid] = acc;
        }
        __syncthreads();

        // phase 7: final eq_linear -> global
        if (tid < 32) {
            const int m = tid >> 2, d = tid & 3;
            const int l = (d == 0) ? 0 : 1;
            float a = (d == 0) ? S.ob[m] : 0.0f;
            #pragma unroll
            for (int mp = 0; mp < MULT; mp++)
                a = fmaf(S.ow[(l * MULT + m) * MULT + mp], S.ao[mp * 4 + d], a);
            out[n * 32 + tid] = a;
        }

        // ---- commit next node's inputs into the other buffer, then publish
        if (pf) {
            const int nb = pb ^ 1;
            S.ef[nb][pe][pi]   = pf_ef;
            S.fsrc[nb][pe][pi] = pf_fs;
            if (parr == 0)      S.bas1[nb][0][peb][px] = pf_bas;
            else if (parr == 1) S.bas2[nb][0][peb][px] = pf_bas;
            else if (parr == 2) S.bas1[nb][1][peb][px] = pf_bas;
            else                S.bas2[nb][1][peb][px] = pf_bas;
            if (tid < 32) S.fnode[nb][tid] = pf_fn;
        }
        __syncthreads();
    }
}

extern "C" void kernel_launch(void* const* d_in, const int* in_sizes, int n_in,
                              void* d_out, int out_size) {
    const float* bk1  = (const float*)d_in[0];
    const float* bk2  = (const float*)d_in[1];
    const float* bv1  = (const float*)d_in[2];
    const float* bv2  = (const float*)d_in[3];
    const float* ef   = (const float*)d_in[4];
    const float* fin  = (const float*)d_in[5];
    const float* q_w  = (const float*)d_in[6];
    const float* q_b  = (const float*)d_in[7];
    const float* k_w1 = (const float*)d_in[8];
    const float* k_b1 = (const float*)d_in[9];
    const float* k_w2 = (const float*)d_in[10];
    const float* k_b2 = (const float*)d_in[11];
    const float* v_w1 = (const float*)d_in[12];
    const float* v_b1 = (const float*)d_in[13];
    const float* v_w2 = (const float*)d_in[14];
    const float* v_b2 = (const float*)d_in[15];
    const float* o_w  = (const float*)d_in[16];
    const float* o_b  = (const float*)d_in[17];
    const int*   nidx = (const int*)d_in[18];
    float* out = (float*)d_out;

    int sms = 148;
    cudaDeviceGetAttribute(&sms, cudaDevAttrMultiProcessorCount, 0);
    if (sms <= 0) sms = 148;

    const int smem = (int)sizeof(SmemT);
    cudaFuncSetAttribute(eqattn_kernel,
                         cudaFuncAttributeMaxDynamicSharedMemorySize, smem);

    eqattn_kernel<<<sms, 512, smem>>>(
        bk1, bk2, bv1, bv2, ef, fin,
        q_w, q_b, k_w1, k_b1, k_w2, k_b2,
        v_w1, v_b1, v_w2, v_b2, o_w, o_b,
        nidx, out);
}